// round 1
// baseline (speedup 1.0000x reference)
#include <cuda_runtime.h>

typedef unsigned long long u64;

#define D_F 16
#define HID 16

// ---- f32x2 packed helpers (Blackwell FFMA2 path) ----
__device__ __forceinline__ u64 ffma2(u64 a, u64 b, u64 c) {
    u64 r;
    asm("fma.rn.f32x2 %0, %1, %2, %3;" : "=l"(r) : "l"(a), "l"(b), "l"(c));
    return r;
}
__device__ __forceinline__ u64 pack2(float v) {
    u64 r; unsigned i = __float_as_uint(v);
    asm("mov.b64 %0, {%1, %1};" : "=l"(r) : "r"(i));
    return r;
}
__device__ __forceinline__ u64 pack2f(float lo, float hi) {
    u64 r;
    asm("mov.b64 %0, {%1, %2};" : "=l"(r)
        : "r"(__float_as_uint(lo)), "r"(__float_as_uint(hi)));
    return r;
}
__device__ __forceinline__ u64 relu2(u64 v) {
    unsigned lo, hi;
    asm("mov.b64 {%0, %1}, %2;" : "=r"(lo), "=r"(hi) : "l"(v));
    float flo = fmaxf(__uint_as_float(lo), 0.0f);
    float fhi = fmaxf(__uint_as_float(hi), 0.0f);
    return pack2f(flo, fhi);
}
__device__ __forceinline__ float lo_of(u64 v) {
    unsigned lo, hi;
    asm("mov.b64 {%0, %1}, %2;" : "=r"(lo), "=r"(hi) : "l"(v));
    return __uint_as_float(lo);
}

__global__ __launch_bounds__(128, 3)
void fields_kernel(const float* __restrict__ x,
                   const float* __restrict__ W1, const float* __restrict__ b1,
                   const float* __restrict__ W2, const float* __restrict__ b2,
                   const float* __restrict__ W3, const float* __restrict__ b3,
                   float* __restrict__ out, int N)
{
    // Weights duplicated as (w,w) f32x2 payloads -> no per-use pack MOV.
    __shared__ __align__(16) u64 sW1[D_F * HID * 3];   // [d][h][c]
    __shared__ __align__(16) u64 sW2[D_F * HID * HID]; // [d][g][h]
    __shared__ __align__(16) u64 sW3[D_F * 3 * HID];   // [d][o][h]
    __shared__ float sB1[D_F * HID], sB2[D_F * HID], sB3[D_F * 3];

    const int tid = threadIdx.x;
    for (int i = tid; i < D_F * HID * 3;   i += blockDim.x) sW1[i] = pack2(W1[i]);
    for (int i = tid; i < D_F * HID * HID; i += blockDim.x) sW2[i] = pack2(W2[i]);
    for (int i = tid; i < D_F * 3 * HID;   i += blockDim.x) sW3[i] = pack2(W3[i]);
    for (int i = tid; i < D_F * HID; i += blockDim.x) { sB1[i] = b1[i]; sB2[i] = b2[i]; }
    for (int i = tid; i < D_F * 3;   i += blockDim.x) sB3[i] = b3[i];
    __syncthreads();

    const int q    = blockIdx.x * blockDim.x + tid;
    const int base = q * 4;

    if (base + 3 < N) {
        // 4 points per thread as two f32x2 pairs (A = pts 0,1; B = pts 2,3)
        u64 xA[3], xB[3];
        #pragma unroll
        for (int c = 0; c < 3; c++) {
            ulonglong2 v = *reinterpret_cast<const ulonglong2*>(x + (size_t)c * N + base);
            xA[c] = v.x; xB[c] = v.y;
        }

        #pragma unroll 1
        for (int d = 0; d < D_F; d++) {
            // ---- layer 1: [16,3] @ x + b1, relu ----
            u64 h1A[HID], h1B[HID];
            const u64*   w1  = sW1 + d * HID * 3;
            const float* bb1 = sB1 + d * HID;
            #pragma unroll
            for (int h = 0; h < HID; h++) {
                u64 a = pack2(bb1[h]); u64 b = a;
                u64 w0 = w1[h * 3 + 0], wc1 = w1[h * 3 + 1], wc2 = w1[h * 3 + 2];
                a = ffma2(w0,  xA[0], a);  b = ffma2(w0,  xB[0], b);
                a = ffma2(wc1, xA[1], a);  b = ffma2(wc1, xB[1], b);
                a = ffma2(wc2, xA[2], a);  b = ffma2(wc2, xB[2], b);
                h1A[h] = relu2(a); h1B[h] = relu2(b);
            }

            // ---- layer 2: [16,16] @ h1 + b2, relu ----
            u64 h2A[HID], h2B[HID];
            const u64*   w2b = sW2 + d * HID * HID;
            const float* bb2 = sB2 + d * HID;
            #pragma unroll
            for (int g = 0; g < HID; g++) {
                u64 a = pack2(bb2[g]); u64 b = a;
                const ulonglong2* wr = reinterpret_cast<const ulonglong2*>(w2b + g * HID);
                #pragma unroll
                for (int h2 = 0; h2 < HID / 2; h2++) {
                    ulonglong2 w = wr[h2];  // LDS.128: two dup-weights
                    a = ffma2(w.x, h1A[2 * h2],     a);  b = ffma2(w.x, h1B[2 * h2],     b);
                    a = ffma2(w.y, h1A[2 * h2 + 1], a);  b = ffma2(w.y, h1B[2 * h2 + 1], b);
                }
                h2A[g] = relu2(a); h2B[g] = relu2(b);
            }

            // ---- layer 3: [3,16] @ h2 + b3, store ----
            #pragma unroll
            for (int o = 0; o < 3; o++) {
                u64 a = pack2(sB3[d * 3 + o]); u64 b = a;
                const ulonglong2* wr =
                    reinterpret_cast<const ulonglong2*>(sW3 + (d * 3 + o) * HID);
                #pragma unroll
                for (int h2 = 0; h2 < HID / 2; h2++) {
                    ulonglong2 w = wr[h2];
                    a = ffma2(w.x, h2A[2 * h2],     a);  b = ffma2(w.x, h2B[2 * h2],     b);
                    a = ffma2(w.y, h2A[2 * h2 + 1], a);  b = ffma2(w.y, h2B[2 * h2 + 1], b);
                }
                *reinterpret_cast<ulonglong2*>(out + (size_t)(d * 3 + o) * N + base) =
                    make_ulonglong2(a, b);
            }
        }
    } else {
        // scalar tail (N % 4 != 0 safety; unused for N = 1e6)
        for (int p = base; p < N && p >= 0; p++) {
            float xs[3];
            #pragma unroll
            for (int c = 0; c < 3; c++) xs[c] = x[(size_t)c * N + p];
            for (int d = 0; d < D_F; d++) {
                float h1[HID], h2[HID];
                for (int h = 0; h < HID; h++) {
                    float s = sB1[d * HID + h];
                    for (int c = 0; c < 3; c++)
                        s += lo_of(sW1[(d * HID + h) * 3 + c]) * xs[c];
                    h1[h] = fmaxf(s, 0.0f);
                }
                for (int g = 0; g < HID; g++) {
                    float s = sB2[d * HID + g];
                    for (int h = 0; h < HID; h++)
                        s += lo_of(sW2[(d * HID + g) * HID + h]) * h1[h];
                    h2[g] = fmaxf(s, 0.0f);
                }
                for (int o = 0; o < 3; o++) {
                    float s = sB3[d * 3 + o];
                    for (int h = 0; h < HID; h++)
                        s += lo_of(sW3[(d * 3 + o) * HID + h]) * h2[h];
                    out[(size_t)(d * 3 + o) * N + p] = s;
                }
            }
        }
    }
}

extern "C" void kernel_launch(void* const* d_in, const int* in_sizes, int n_in,
                              void* d_out, int out_size)
{
    const float* x  = (const float*)d_in[0];
    const float* W1 = (const float*)d_in[1];
    const float* b1 = (const float*)d_in[2];
    const float* W2 = (const float*)d_in[3];
    const float* b2 = (const float*)d_in[4];
    const float* W3 = (const float*)d_in[5];
    const float* b3 = (const float*)d_in[6];
    float* out = (float*)d_out;

    const int N  = in_sizes[0] / 3;        // x is [1,3,N]
    const int nq = (N + 3) / 4;            // 4 points per thread
    const int grid = (nq + 127) / 128;

    fields_kernel<<<grid, 128>>>(x, W1, b1, W2, b2, W3, b3, out, N);
}